// round 9
// baseline (speedup 1.0000x reference)
#include <cuda_runtime.h>
#include <cstdint>

// Problem constants
#define BB 8
#define NN 1024
#define CC 768
#define HH 12
#define DD 64
#define ROWS (BB * NN)          // 8192
#define QKVC (3 * CC)           // 2304

// Scratch (allocation-free rule: __device__ globals)
__device__ float g_qkv[ROWS * QKVC];                 // 75.5 MB
__device__ float g_heads[ROWS * CC];                 // 25 MB
__device__ float g_attn_fb[BB * HH * NN * NN];       // 402 MB fallback if attn not in d_out

// ---------------------------------------------------------------------------
// TF32 helpers (3xTF32 split-precision on the tensor pipe)
// ---------------------------------------------------------------------------
__device__ __forceinline__ uint32_t f2tf(float x) {
    uint32_t r;
    asm("cvt.rna.tf32.f32 %0, %1;" : "=r"(r) : "f"(x));
    return r;
}

__device__ __forceinline__ void mma8(float (&c)[4], const uint32_t (&a)[4],
                                     const uint32_t (&b)[2]) {
    asm volatile(
        "mma.sync.aligned.m16n8k8.row.col.f32.tf32.tf32.f32 "
        "{%0,%1,%2,%3},{%4,%5,%6,%7},{%8,%9},{%0,%1,%2,%3};"
        : "+f"(c[0]), "+f"(c[1]), "+f"(c[2]), "+f"(c[3])
        : "r"(a[0]), "r"(a[1]), "r"(a[2]), "r"(a[3]), "r"(b[0]), "r"(b[1]));
}

#define BKK 16
#define PAD 136   // frag LDS bank = 8*tig + gid -> conflict-free
#define PVB 72    // 72%32=8 -> b-frag bank 8*tig+gid conflict-free

// Dynamic smem byte sizes (static __shared__ caps at 48KB; these exceed it)
#define GEMM_SMEM  (2 * (2 * 2 * BKK * PAD) * 4)                 // 69,632 B
#define PV_SMEM    ((2 * 2 * BKK * PAD + 2 * 2 * BKK * PVB) * 4) // 53,248 B

__device__ __forceinline__ void split_store(uint32_t (*s)[BKK][PAD], int k, int r,
                                            float4 v) {
    float xs[4] = {v.x, v.y, v.z, v.w};
#pragma unroll
    for (int j = 0; j < 4; j++) {
        uint32_t hi = f2tf(xs[j]);
        s[0][k + j][r] = hi;
        s[1][k + j][r] = f2tf(xs[j] - __uint_as_float(hi));
    }
}

// ---------------------------------------------------------------------------
// TF32 tensor-core GEMM (NT): C[M,N] = A[M,K] * B[N,K]^T + bias[N]
// 2-stage smem double buffering: MMA on stage kt&1 while staging kt+1.
// ---------------------------------------------------------------------------
__global__ __launch_bounds__(256) void gemm_tf32_nt(
    const float* __restrict__ A, const float* __restrict__ Bm,
    const float* __restrict__ bias, float* __restrict__ C,
    int M, int N, int K)
{
    extern __shared__ __align__(16) uint32_t smem_u[];
    auto As = reinterpret_cast<uint32_t(*)[2][BKK][PAD]>(smem_u);                    // [2][2][BKK][PAD]
    auto Bs = reinterpret_cast<uint32_t(*)[2][BKK][PAD]>(smem_u + 2 * 2 * BKK * PAD);

    const int tid = threadIdx.x;
    const int m0 = blockIdx.y * 128;
    const int n0 = blockIdx.x * 128;
    const int lane = tid & 31, warp = tid >> 5;
    const int gid = lane >> 2, tig = lane & 3;
    const int wm = (warp >> 2) * 64;
    const int wn = (warp & 3) * 32;

    const int lrow = tid >> 2;
    const int lkq = (tid & 3) * 4;
    const float* Ap = A + (size_t)(m0 + lrow) * K + lkq;
    const float* Bp = Bm + (size_t)(n0 + lrow) * K + lkq;
    const size_t rstep = (size_t)64 * K;

    float c[4][4][4];
#pragma unroll
    for (int i = 0; i < 4; i++)
#pragma unroll
        for (int j = 0; j < 4; j++)
#pragma unroll
            for (int q = 0; q < 4; q++) c[i][j][q] = 0.f;

    // Stage tile 0 into buffer 0
    {
        float4 a0 = *(const float4*)(Ap);
        float4 a1 = *(const float4*)(Ap + rstep);
        float4 b0 = *(const float4*)(Bp);
        float4 b1 = *(const float4*)(Bp + rstep);
        split_store(As[0], lkq, lrow, a0);
        split_store(As[0], lkq, lrow + 64, a1);
        split_store(Bs[0], lkq, lrow, b0);
        split_store(Bs[0], lkq, lrow + 64, b1);
    }
    __syncthreads();

    const int nkt = K / BKK;
    for (int kt = 0; kt < nkt; kt++) {
        const int cur = kt & 1, nxt = cur ^ 1;
        float4 pa0, pa1, pb0, pb1;
        if (kt + 1 < nkt) {    // issue next tile's LDGs before the MMA burst
            const float* Ap2 = Ap + (size_t)(kt + 1) * BKK;
            const float* Bp2 = Bp + (size_t)(kt + 1) * BKK;
            pa0 = *(const float4*)(Ap2);
            pa1 = *(const float4*)(Ap2 + rstep);
            pb0 = *(const float4*)(Bp2);
            pb1 = *(const float4*)(Bp2 + rstep);
        }

#pragma unroll
        for (int s = 0; s < 2; s++) {
            const int k0 = s * 8 + tig, k1 = k0 + 4;
            uint32_t ah[4][4], al[4][4], bh[4][2], bl[4][2];
#pragma unroll
            for (int mi = 0; mi < 4; mi++) {
                int ra = wm + mi * 16 + gid;
                ah[mi][0] = As[cur][0][k0][ra];     ah[mi][1] = As[cur][0][k0][ra + 8];
                ah[mi][2] = As[cur][0][k1][ra];     ah[mi][3] = As[cur][0][k1][ra + 8];
                al[mi][0] = As[cur][1][k0][ra];     al[mi][1] = As[cur][1][k0][ra + 8];
                al[mi][2] = As[cur][1][k1][ra];     al[mi][3] = As[cur][1][k1][ra + 8];
            }
#pragma unroll
            for (int ni = 0; ni < 4; ni++) {
                int rb = wn + ni * 8 + gid;
                bh[ni][0] = Bs[cur][0][k0][rb];     bh[ni][1] = Bs[cur][0][k1][rb];
                bl[ni][0] = Bs[cur][1][k0][rb];     bl[ni][1] = Bs[cur][1][k1][rb];
            }
#pragma unroll
            for (int mi = 0; mi < 4; mi++)
#pragma unroll
                for (int ni = 0; ni < 4; ni++) {
                    mma8(c[mi][ni], ah[mi], bl[ni]);
                    mma8(c[mi][ni], al[mi], bh[ni]);
                    mma8(c[mi][ni], ah[mi], bh[ni]);
                }
        }

        if (kt + 1 < nkt) {    // stage next tile into the other buffer (overlaps MMA)
            split_store(As[nxt], lkq, lrow, pa0);
            split_store(As[nxt], lkq, lrow + 64, pa1);
            split_store(Bs[nxt], lkq, lrow, pb0);
            split_store(Bs[nxt], lkq, lrow + 64, pb1);
        }
        __syncthreads();
    }

#pragma unroll
    for (int mi = 0; mi < 4; mi++) {
        int row0 = m0 + wm + mi * 16 + gid;
#pragma unroll
        for (int ni = 0; ni < 4; ni++) {
            int col = n0 + wn + ni * 8 + tig * 2;
            float2 bb = *(const float2*)&bias[col];
            float2 o0 = make_float2(c[mi][ni][0] + bb.x, c[mi][ni][1] + bb.y);
            float2 o1 = make_float2(c[mi][ni][2] + bb.x, c[mi][ni][3] + bb.y);
            *(float2*)&C[(size_t)row0 * N + col] = o0;
            *(float2*)&C[(size_t)(row0 + 8) * N + col] = o1;
        }
    }
}

// ---------------------------------------------------------------------------
// LayerNorm over head_dim=64 for q (part 0, also *SCALE) and k (part 1)
// ---------------------------------------------------------------------------
__global__ __launch_bounds__(256) void ln_qk(
    float* __restrict__ qkv,
    const float* __restrict__ qg, const float* __restrict__ qb,
    const float* __restrict__ kg, const float* __restrict__ kb)
{
    int wid = (blockIdx.x * blockDim.x + threadIdx.x) >> 5;
    int lane = threadIdx.x & 31;
    int ph = wid % 24;
    int row = wid / 24;
    int part = ph / HH;
    int h = ph % HH;

    float* p = qkv + (size_t)row * QKVC + part * CC + h * DD;
    float x0 = p[lane];
    float x1 = p[lane + 32];
    float s = x0 + x1;
    float s2 = x0 * x0 + x1 * x1;
#pragma unroll
    for (int o = 16; o; o >>= 1) {
        s += __shfl_xor_sync(0xffffffffu, s, o);
        s2 += __shfl_xor_sync(0xffffffffu, s2, o);
    }
    float mu = s * (1.f / 64.f);
    float var = s2 * (1.f / 64.f) - mu * mu;
    float inv = rsqrtf(var + 1e-5f);
    const float* g = part ? kg : qg;
    const float* be = part ? kb : qb;
    float scale = part ? 1.0f : 0.125f;   // SCALE = 64^-0.5
    p[lane]      = ((x0 - mu) * inv * g[lane]      + be[lane])      * scale;
    p[lane + 32] = ((x1 - mu) * inv * g[lane + 32] + be[lane + 32]) * scale;
}

// ---------------------------------------------------------------------------
// Scores: batched NT GEMM. S[bh][1024,1024] = Q @ K^T (raw). Double-buffered.
// ---------------------------------------------------------------------------
__global__ __launch_bounds__(256) void scores_tf32(
    const float* __restrict__ qkv, float* __restrict__ attn)
{
    extern __shared__ __align__(16) uint32_t smem_u[];
    auto As = reinterpret_cast<uint32_t(*)[2][BKK][PAD]>(smem_u);
    auto Bs = reinterpret_cast<uint32_t(*)[2][BKK][PAD]>(smem_u + 2 * 2 * BKK * PAD);

    const int tid = threadIdx.x;
    const int m0 = blockIdx.y * 128;
    const int n0 = blockIdx.x * 128;
    const int bh = blockIdx.z;
    const int b = bh / HH, h = bh % HH;
    const float* Aq = qkv + (size_t)b * NN * QKVC + h * DD;   // Q rows, lda QKVC
    const float* Bk = Aq + CC;                                 // K rows
    float* C = attn + (size_t)bh * NN * NN;

    const int lane = tid & 31, warp = tid >> 5;
    const int gid = lane >> 2, tig = lane & 3;
    const int wm = (warp >> 2) * 64;
    const int wn = (warp & 3) * 32;

    const int lrow = tid >> 2;
    const int lkq = (tid & 3) * 4;
    const float* Ap = Aq + (size_t)(m0 + lrow) * QKVC + lkq;
    const float* Bp = Bk + (size_t)(n0 + lrow) * QKVC + lkq;
    const size_t rstep = (size_t)64 * QKVC;

    float c[4][4][4];
#pragma unroll
    for (int i = 0; i < 4; i++)
#pragma unroll
        for (int j = 0; j < 4; j++)
#pragma unroll
            for (int q = 0; q < 4; q++) c[i][j][q] = 0.f;

    {
        float4 a0 = *(const float4*)(Ap);
        float4 a1 = *(const float4*)(Ap + rstep);
        float4 b0 = *(const float4*)(Bp);
        float4 b1 = *(const float4*)(Bp + rstep);
        split_store(As[0], lkq, lrow, a0);
        split_store(As[0], lkq, lrow + 64, a1);
        split_store(Bs[0], lkq, lrow, b0);
        split_store(Bs[0], lkq, lrow + 64, b1);
    }
    __syncthreads();

    for (int kt = 0; kt < 4; kt++) {      // K = 64 = 4 * BKK
        const int cur = kt & 1, nxt = cur ^ 1;
        float4 pa0, pa1, pb0, pb1;
        if (kt + 1 < 4) {
            const float* Ap2 = Ap + (kt + 1) * BKK;
            const float* Bp2 = Bp + (kt + 1) * BKK;
            pa0 = *(const float4*)(Ap2);
            pa1 = *(const float4*)(Ap2 + rstep);
            pb0 = *(const float4*)(Bp2);
            pb1 = *(const float4*)(Bp2 + rstep);
        }

#pragma unroll
        for (int s = 0; s < 2; s++) {
            const int k0 = s * 8 + tig, k1 = k0 + 4;
            uint32_t ah[4][4], al[4][4], bh2[4][2], bl2[4][2];
#pragma unroll
            for (int mi = 0; mi < 4; mi++) {
                int ra = wm + mi * 16 + gid;
                ah[mi][0] = As[cur][0][k0][ra];     ah[mi][1] = As[cur][0][k0][ra + 8];
                ah[mi][2] = As[cur][0][k1][ra];     ah[mi][3] = As[cur][0][k1][ra + 8];
                al[mi][0] = As[cur][1][k0][ra];     al[mi][1] = As[cur][1][k0][ra + 8];
                al[mi][2] = As[cur][1][k1][ra];     al[mi][3] = As[cur][1][k1][ra + 8];
            }
#pragma unroll
            for (int ni = 0; ni < 4; ni++) {
                int rb = wn + ni * 8 + gid;
                bh2[ni][0] = Bs[cur][0][k0][rb];    bh2[ni][1] = Bs[cur][0][k1][rb];
                bl2[ni][0] = Bs[cur][1][k0][rb];    bl2[ni][1] = Bs[cur][1][k1][rb];
            }
#pragma unroll
            for (int mi = 0; mi < 4; mi++)
#pragma unroll
                for (int ni = 0; ni < 4; ni++) {
                    mma8(c[mi][ni], ah[mi], bl2[ni]);
                    mma8(c[mi][ni], al[mi], bh2[ni]);
                    mma8(c[mi][ni], ah[mi], bh2[ni]);
                }
        }

        if (kt + 1 < 4) {
            split_store(As[nxt], lkq, lrow, pa0);
            split_store(As[nxt], lkq, lrow + 64, pa1);
            split_store(Bs[nxt], lkq, lrow, pb0);
            split_store(Bs[nxt], lkq, lrow + 64, pb1);
        }
        __syncthreads();
    }

#pragma unroll
    for (int mi = 0; mi < 4; mi++) {
        int row0 = m0 + wm + mi * 16 + gid;
#pragma unroll
        for (int ni = 0; ni < 4; ni++) {
            int col = n0 + wn + ni * 8 + tig * 2;
            *(float2*)&C[(size_t)row0 * NN + col]       = make_float2(c[mi][ni][0], c[mi][ni][1]);
            *(float2*)&C[(size_t)(row0 + 8) * NN + col] = make_float2(c[mi][ni][2], c[mi][ni][3]);
        }
    }
}

// ---------------------------------------------------------------------------
// Row softmax in place: one warp per row, row held in registers.
// (measured R7: 114us @ 82% of HBM spec — done)
// ---------------------------------------------------------------------------
__global__ __launch_bounds__(256) void softmax_rows(float* __restrict__ attn)
{
    const int warp = threadIdx.x >> 5, lane = threadIdx.x & 31;
    const size_t row = (size_t)blockIdx.x * 8 + warp;
    float* p = attn + row * NN;

    float4 v[8];
    float m = -1e30f;
#pragma unroll
    for (int it = 0; it < 8; it++) {
        v[it] = *(const float4*)&p[it * 128 + lane * 4];
        m = fmaxf(m, fmaxf(fmaxf(v[it].x, v[it].y), fmaxf(v[it].z, v[it].w)));
    }
#pragma unroll
    for (int o = 16; o; o >>= 1) m = fmaxf(m, __shfl_xor_sync(0xffffffffu, m, o));
    float sum = 0.f;
#pragma unroll
    for (int it = 0; it < 8; it++) {
        v[it].x = __expf(v[it].x - m); v[it].y = __expf(v[it].y - m);
        v[it].z = __expf(v[it].z - m); v[it].w = __expf(v[it].w - m);
        sum += v[it].x + v[it].y + v[it].z + v[it].w;
    }
#pragma unroll
    for (int o = 16; o; o >>= 1) sum += __shfl_xor_sync(0xffffffffu, sum, o);
    float inv = 1.f / sum;
#pragma unroll
    for (int it = 0; it < 8; it++) {
        v[it].x *= inv; v[it].y *= inv; v[it].z *= inv; v[it].w *= inv;
        *(float4*)&p[it * 128 + lane * 4] = v[it];
    }
}

// ---------------------------------------------------------------------------
// PV: batched NN GEMM. heads = P @ V. Double-buffered. Grid (8, 96).
// ---------------------------------------------------------------------------
__global__ __launch_bounds__(256) void pv_tf32(
    const float* __restrict__ attn, const float* __restrict__ qkv,
    float* __restrict__ heads)
{
    extern __shared__ __align__(16) uint32_t smem_u[];
    auto As = reinterpret_cast<uint32_t(*)[2][BKK][PAD]>(smem_u);
    auto Bs = reinterpret_cast<uint32_t(*)[2][BKK][PVB]>(smem_u + 2 * 2 * BKK * PAD);

    const int tid = threadIdx.x;
    const int m0 = blockIdx.x * 128;
    const int bh = blockIdx.y;
    const int b = bh / HH, h = bh % HH;
    const float* A = attn + (size_t)bh * NN * NN;
    const float* V = qkv + (size_t)b * NN * QKVC + 2 * CC + h * DD;

    const int lane = tid & 31, warp = tid >> 5;
    const int gid = lane >> 2, tig = lane & 3;
    const int wm = (warp >> 1) * 32;
    const int wn = (warp & 1) * 32;

    const int alr = tid >> 1, alk = (tid & 1) * 8;
    const int blr = tid >> 4, bnq = (tid & 15) * 4;

    const float* Apt = A + (size_t)(m0 + alr) * NN + alk;
    const float* Bpt = V + (size_t)blr * QKVC + bnq;

    float c[2][4][4];
#pragma unroll
    for (int i = 0; i < 2; i++)
#pragma unroll
        for (int j = 0; j < 4; j++)
#pragma unroll
            for (int q = 0; q < 4; q++) c[i][j][q] = 0.f;

    {
        float4 a0 = *(const float4*)(Apt);
        float4 a1 = *(const float4*)(Apt + 4);
        float4 b0 = *(const float4*)(Bpt);
        split_store(As[0], alk, alr, a0);
        split_store(As[0], alk + 4, alr, a1);
        float xs[4] = {b0.x, b0.y, b0.z, b0.w};
#pragma unroll
        for (int j = 0; j < 4; j++) {
            uint32_t hi = f2tf(xs[j]);
            Bs[0][0][blr][bnq + j] = hi;
            Bs[0][1][blr][bnq + j] = f2tf(xs[j] - __uint_as_float(hi));
        }
    }
    __syncthreads();

    for (int kt = 0; kt < 64; kt++) {
        const int cur = kt & 1, nxt = cur ^ 1;
        float4 pa0, pa1, pb0;
        if (kt + 1 < 64) {
            const float* Ap2 = Apt + (kt + 1) * BKK;
            const float* Bp2 = Bpt + (size_t)(kt + 1) * BKK * QKVC;
            pa0 = *(const float4*)(Ap2);
            pa1 = *(const float4*)(Ap2 + 4);
            pb0 = *(const float4*)(Bp2);
        }

#pragma unroll
        for (int s = 0; s < 2; s++) {
            const int k0 = s * 8 + tig, k1 = k0 + 4;
            uint32_t ah[2][4], al[2][4], bh2[4][2], bl2[4][2];
#pragma unroll
            for (int mi = 0; mi < 2; mi++) {
                int ra = wm + mi * 16 + gid;
                ah[mi][0] = As[cur][0][k0][ra];     ah[mi][1] = As[cur][0][k0][ra + 8];
                ah[mi][2] = As[cur][0][k1][ra];     ah[mi][3] = As[cur][0][k1][ra + 8];
                al[mi][0] = As[cur][1][k0][ra];     al[mi][1] = As[cur][1][k0][ra + 8];
                al[mi][2] = As[cur][1][k1][ra];     al[mi][3] = As[cur][1][k1][ra + 8];
            }
#pragma unroll
            for (int ni = 0; ni < 4; ni++) {
                int rb = wn + ni * 8 + gid;
                bh2[ni][0] = Bs[cur][0][k0][rb];    bh2[ni][1] = Bs[cur][0][k1][rb];
                bl2[ni][0] = Bs[cur][1][k0][rb];    bl2[ni][1] = Bs[cur][1][k1][rb];
            }
#pragma unroll
            for (int mi = 0; mi < 2; mi++)
#pragma unroll
                for (int ni = 0; ni < 4; ni++) {
                    mma8(c[mi][ni], ah[mi], bl2[ni]);
                    mma8(c[mi][ni], al[mi], bh2[ni]);
                    mma8(c[mi][ni], ah[mi], bh2[ni]);
                }
        }

        if (kt + 1 < 64) {
            split_store(As[nxt], alk, alr, pa0);
            split_store(As[nxt], alk + 4, alr, pa1);
            float xs[4] = {pb0.x, pb0.y, pb0.z, pb0.w};
#pragma unroll
            for (int j = 0; j < 4; j++) {
                uint32_t hi = f2tf(xs[j]);
                Bs[nxt][0][blr][bnq + j] = hi;
                Bs[nxt][1][blr][bnq + j] = f2tf(xs[j] - __uint_as_float(hi));
            }
        }
        __syncthreads();
    }

#pragma unroll
    for (int mi = 0; mi < 2; mi++) {
        int row0 = m0 + wm + mi * 16 + gid;
#pragma unroll
        for (int ni = 0; ni < 4; ni++) {
            int col = wn + ni * 8 + tig * 2;
            *(float2*)&heads[((size_t)b * NN + row0) * CC + h * DD + col] =
                make_float2(c[mi][ni][0], c[mi][ni][1]);
            *(float2*)&heads[((size_t)b * NN + row0 + 8) * CC + h * DD + col] =
                make_float2(c[mi][ni][2], c[mi][ni][3]);
        }
    }
}

// ---------------------------------------------------------------------------
// Launch: qkv GEMM -> LN -> scores GEMM -> softmax -> PV GEMM -> proj GEMM
// ---------------------------------------------------------------------------
extern "C" void kernel_launch(void* const* d_in, const int* in_sizes, int n_in,
                              void* d_out, int out_size)
{
    const float* x      = (const float*)d_in[0];
    const float* qkv_w  = (const float*)d_in[1];
    const float* qkv_b  = (const float*)d_in[2];
    const float* qg     = (const float*)d_in[3];
    const float* qbeta  = (const float*)d_in[4];
    const float* kg     = (const float*)d_in[5];
    const float* kbeta  = (const float*)d_in[6];
    const float* proj_w = (const float*)d_in[7];
    const float* proj_b = (const float*)d_in[8];
    float* out = (float*)d_out;

    float *qkv_ptr, *heads_ptr, *attn_fb;
    cudaGetSymbolAddress((void**)&qkv_ptr, g_qkv);
    cudaGetSymbolAddress((void**)&heads_ptr, g_heads);
    cudaGetSymbolAddress((void**)&attn_fb, g_attn_fb);

    const long OUT_E  = (long)ROWS * CC;                 // 6,291,456
    const long ATTN_E = (long)BB * HH * NN * NN;         // 100,663,296
    float* attn_ptr = ((long)out_size >= OUT_E + ATTN_E) ? (out + OUT_E) : attn_fb;

    cudaFuncSetAttribute(gemm_tf32_nt, cudaFuncAttributeMaxDynamicSharedMemorySize, GEMM_SMEM);
    cudaFuncSetAttribute(scores_tf32, cudaFuncAttributeMaxDynamicSharedMemorySize, GEMM_SMEM);
    cudaFuncSetAttribute(pv_tf32, cudaFuncAttributeMaxDynamicSharedMemorySize, PV_SMEM);

    // 1. qkv = x @ qkv_w^T + qkv_b
    gemm_tf32_nt<<<dim3(QKVC / 128, ROWS / 128), 256, GEMM_SMEM>>>(
        x, qkv_w, qkv_b, qkv_ptr, ROWS, QKVC, CC);
    // 2. LayerNorm q (with *SCALE) and k, in place
    ln_qk<<<(ROWS * 24) / 8, 256>>>(qkv_ptr, qg, qbeta, kg, kbeta);
    // 3. raw scores into attn buffer
    scores_tf32<<<dim3(8, 8, BB * HH), 256, GEMM_SMEM>>>(qkv_ptr, attn_ptr);
    // 4. softmax in place (produces final attn output)
    softmax_rows<<<BB * HH * NN / 8, 256>>>(attn_ptr);
    // 5. heads = attn @ V
    pv_tf32<<<dim3(8, BB * HH), 256, PV_SMEM>>>(attn_ptr, qkv_ptr, heads_ptr);
    // 6. out = heads @ proj_w^T + proj_b
    gemm_tf32_nt<<<dim3(CC / 128, ROWS / 128), 256, GEMM_SMEM>>>(
        heads_ptr, proj_w, proj_b, out, ROWS, CC, CC);
}